// round 9
// baseline (speedup 1.0000x reference)
#include <cuda_runtime.h>
#include <cuda_fp16.h>
#include <cstdint>

// ---------------- problem constants ----------------
constexpr int Dm = 1024;
constexpr int Hm = 4096;
constexpr int Em = 8;
constexpr int Tm = 2048;
constexpr int NG = 9;                    // 8 routed + shared at slot 8
constexpr int HD = Hm * Dm;              // 1<<22
constexpr int MAXROWS = Tm * 3;          // 6144
constexpr int PADROWS = MAXROWS + 256;   // pad to 256-row tile granularity
constexpr int MAXTILES = 64;
constexpr int TILE_M = 256;
constexpr int SMEM_BYTES = 147456;       // 3 stages x (32KB A + 16KB B)

// ---------------- device scratch (static, no runtime alloc) ----------------
__device__ __half g_W1h[(size_t)NG * HD];
__device__ __half g_W2h[(size_t)NG * HD];
__device__ __half g_xh[(size_t)Tm * Dm];
__device__ __half g_h[(size_t)PADROWS * Hm];
__device__ float  g_o2[(size_t)PADROWS * Dm];
__device__ int    g_cnt9[NG];
__device__ int    g_off9[NG];
__device__ int    g_fill[Em];
__device__ int    g_tok[PADROWS];
__device__ int    g_slot[Tm * 2];
__device__ float  g_cw[Tm * 2];
__device__ int    g_topi[Tm * 2];
__device__ float  g_topw[Tm * 2];
__device__ int2   g_tiles[MAXTILES];
__device__ int    g_ntiles;

// ---------------- ptx helpers (sm_103-safe) -----
__device__ __forceinline__ uint32_t smem_u32(const void* p) {
    uint32_t a;
    asm("{ .reg .u64 t; cvta.to.shared.u64 t, %1; cvt.u32.u64 %0, t; }" : "=r"(a) : "l"(p));
    return a;
}
__device__ __forceinline__ void cp_async16(uint32_t saddr, const void* gaddr) {
    asm volatile("cp.async.cg.shared.global [%0], [%1], 16;" :: "r"(saddr), "l"(gaddr) : "memory");
}
__device__ __forceinline__ void cp_commit() {
    asm volatile("cp.async.commit_group;" ::: "memory");
}
template <int N>
__device__ __forceinline__ void cp_wait() {
    asm volatile("cp.async.wait_group %0;" :: "n"(N) : "memory");
}
__device__ __forceinline__ void ldsm4(uint32_t* r, uint32_t a) {
    asm volatile("ldmatrix.sync.aligned.m8n8.x4.shared.b16 {%0,%1,%2,%3}, [%4];"
        : "=r"(r[0]), "=r"(r[1]), "=r"(r[2]), "=r"(r[3]) : "r"(a));
}
__device__ __forceinline__ void mma16816(float* c, const uint32_t* a, const uint32_t* b) {
    asm volatile("mma.sync.aligned.m16n8k16.row.col.f32.f16.f16.f32 "
        "{%0,%1,%2,%3}, {%4,%5,%6,%7}, {%8,%9}, {%0,%1,%2,%3};"
        : "+f"(c[0]), "+f"(c[1]), "+f"(c[2]), "+f"(c[3])
        : "r"(a[0]), "r"(a[1]), "r"(a[2]), "r"(a[3]), "r"(b[0]), "r"(b[1]));
}
__device__ __forceinline__ float gelu_exact(float v) {
    return 0.5f * v * (1.0f + erff(v * 0.70710678118654752f));
}

// ================== kernel: fp32 -> fp16 weight conversion (+ counter zero) ==================
__global__ void k_convert(const float* __restrict__ W1, const float* __restrict__ Ws1,
                          const float* __restrict__ W2, const float* __restrict__ Ws2) {
    if (blockIdx.x == 0) {
        for (int i = threadIdx.x; i < PADROWS; i += blockDim.x) g_tok[i] = 0;
        if (threadIdx.x < Em) g_fill[threadIdx.x] = 0;
        if (threadIdx.x < NG) g_cnt9[threadIdx.x] = 0;
    }
    long i4 = (long)blockIdx.x * blockDim.x + threadIdx.x;
    long elem = i4 * 4;
    const long WPART = (long)NG * HD;
    const float* src;
    __half* dst;
    if (elem < WPART) {
        int e = (int)(elem >> 22);
        int off = (int)(elem & (HD - 1));
        src = (e < Em) ? (W1 + (size_t)e * HD + off) : (Ws1 + off);
        dst = g_W1h + elem;
    } else {
        long el = elem - WPART;
        if (el >= WPART) return;
        int e = (int)(el >> 22);
        int off = (int)(el & (HD - 1));
        src = (e < Em) ? (W2 + (size_t)e * HD + off) : (Ws2 + off);
        dst = g_W2h + el;
    }
    float4 v = *(const float4*)src;
    __half2 lo = __floats2half2_rn(v.x, v.y);
    __half2 hi = __floats2half2_rn(v.z, v.w);
    struct __align__(8) H4 { __half2 a, b; };
    *(H4*)dst = H4{lo, hi};
}

// ================== kernel: gating + x->fp16 ==================
__global__ void k_gating(const float* __restrict__ x, const float* __restrict__ Wg,
                         const float* __restrict__ bg, const float* __restrict__ bias) {
    int wid = threadIdx.x >> 5, lane = threadIdx.x & 31;
    int t = blockIdx.x * 8 + wid;
    float xr[32];
#pragma unroll
    for (int i = 0; i < 32; i++) xr[i] = x[(size_t)t * Dm + i * 32 + lane];
#pragma unroll
    for (int i = 0; i < 32; i++) g_xh[(size_t)t * Dm + i * 32 + lane] = __float2half_rn(xr[i]);
    float s[Em];
#pragma unroll
    for (int e = 0; e < Em; e++) {
        float acc = 0.f;
#pragma unroll
        for (int i = 0; i < 32; i++) acc = fmaf(xr[i], Wg[e * Dm + i * 32 + lane], acc);
#pragma unroll
        for (int off = 16; off >= 1; off >>= 1) acc += __shfl_xor_sync(0xFFFFFFFFu, acc, off);
        s[e] = 1.f / (1.f + expf(-(acc + bg[e] + bias[e])));
    }
    if (lane == 0) {
        int i0 = 0;
#pragma unroll
        for (int e = 1; e < Em; e++) if (s[e] > s[i0]) i0 = e;
        int i1 = -1;
#pragma unroll
        for (int e = 0; e < Em; e++) if (e != i0 && (i1 < 0 || s[e] > s[i1])) i1 = e;
        g_topi[2 * t] = i0;     g_topw[2 * t] = s[i0];
        g_topi[2 * t + 1] = i1; g_topw[2 * t + 1] = s[i1];
        atomicAdd(&g_cnt9[i0], 1);
        atomicAdd(&g_cnt9[i1], 1);
    }
}

// ================== kernel: routing (offsets + 256-row tile table + scatter) ==================
__global__ __launch_bounds__(1024) void k_route() {
    if (threadIdx.x == 0) {
        g_cnt9[8] = Tm;
        g_off9[8] = 0;
        int nt = 0;
        for (int rs = 0; rs < Tm; rs += TILE_M) g_tiles[nt++] = make_int2(8, rs);
        int p = Tm;
        for (int e = 0; e < Em; e++) {
            g_off9[e] = p;
            p += g_cnt9[e];
            for (int rs = 0; rs < g_cnt9[e]; rs += TILE_M) g_tiles[nt++] = make_int2(e, rs);
        }
        g_ntiles = nt;
    }
    __syncthreads();
#pragma unroll
    for (int r = 0; r < 2; ++r) {
        int t = threadIdx.x + r * 1024;
        g_tok[t] = t; // shared slots occupy [0, Tm)
#pragma unroll
        for (int k = 0; k < 2; k++) {
            int e = g_topi[2 * t + k];
            float w = g_topw[2 * t + k];
            int pos = atomicAdd(&g_fill[e], 1);
            int slot = g_off9[e] + pos;
            g_tok[slot] = t;
            g_slot[2 * t + k] = slot;
            g_cw[2 * t + k] = w;
        }
    }
}

// ================== grouped GEMM, 256x128 tile, HMMA m16n8k16 f32-acc ==================
// 512 threads = 16 warps in 8(m) x 2(n); each warp computes 32x64 (64 acc regs).
// 3-stage cp.async pipeline (stage = 32KB A + 16KB B), one syncthreads per K=64 chunk.
// 1 CTA/SM (regs 128 x 512 thr = full RF), same 16 warps/SM as R8 but:
//   - L2 traffic -40% (A amortized over 2x rows per B fetch)
//   - barriers per HMMA halved
// MODE 1: h = gelu(x @ W1^T + b1) -> g_h (fp16), K = 1024
// MODE 2: o2 = h @ W2^T + b2      -> g_o2 (fp32), K = 4096
template <int MODE>
__global__ __launch_bounds__(512, 1) void k_gemm(
    const float* __restrict__ b1, const float* __restrict__ bs1,
    const float* __restrict__ b2, const float* __restrict__ bs2)
{
    extern __shared__ char smem[];
    const int tid = threadIdx.x;
    const int lane = tid & 31, wid = tid >> 5;
    const int wm = wid >> 1, wn = wid & 1;   // 8 x 2

    int mt = blockIdx.x;
    if (mt >= g_ntiles) return;
    int2 tl = g_tiles[mt];
    const int e = tl.x, rs = tl.y;
    const int rows_valid = g_cnt9[e] - rs;
    const int slot_base = g_off9[e] + rs;
    const int nbase = blockIdx.y * 128;

    constexpr int K = (MODE == 1) ? Dm : Hm;
    constexpr int NK = K / 64;
    constexpr uint32_t STAGE = 49152u;      // 32KB A + 16KB B

    uint32_t sb = smem_u32(smem);

    // ---- A copy: thread t -> row t>>1 (0..255), chunks (t&1)*4+v (4x cp.async16)
    const int crowA = tid >> 1;
    const __half* Asrc;
    if (MODE == 1) {
        int tok = g_tok[slot_base + crowA];
        Asrc = g_xh + (size_t)tok * Dm;
    } else {
        Asrc = g_h + (size_t)(slot_base + crowA) * Hm;
    }
    uint32_t cdstA[4];
#pragma unroll
    for (int v = 0; v < 4; ++v) {
        int ch = (tid & 1) * 4 + v;
        cdstA[v] = (uint32_t)crowA * 128u + (uint32_t)((ch ^ (crowA & 7)) << 4);
    }
    // ---- B copy: thread t -> row t>>2 (0..127), chunks (t&3)*2+v (2x cp.async16)
    const int crowB = tid >> 2;
    const __half* Bsrc = ((MODE == 1) ? g_W1h : g_W2h)
                         + (size_t)e * HD + (size_t)(nbase + crowB) * K;
    uint32_t cdstB[2];
#pragma unroll
    for (int v = 0; v < 2; ++v) {
        int ch = (tid & 3) * 2 + v;
        cdstB[v] = (uint32_t)crowB * 128u + (uint32_t)((ch ^ (crowB & 7)) << 4);
    }

    // ---- ldmatrix lane-derived offsets (non-trans x4) ----
    const int m4 = lane >> 3;
    const int aro = ((m4 & 1) << 3) + (lane & 7);   // A: row offset in 16-row tile
    const int aco = m4 >> 1;                        // A: k-chunk offset (0/1)
    const int bro = ((m4 >> 1) << 3) + (lane & 7);  // B: n-row offset in 16-row pair
    const int bco = m4 & 1;                         // B: k-chunk offset (0/1)

    float acc[2][8][4];
#pragma unroll
    for (int a = 0; a < 2; ++a)
#pragma unroll
        for (int b = 0; b < 8; ++b)
#pragma unroll
            for (int c = 0; c < 4; ++c) acc[a][b][c] = 0.f;

    // issue a full K=64 chunk (A+B) into stage slot
    auto issue = [&](int i) {
        uint32_t stg = sb + (uint32_t)(i % 3) * STAGE;
#pragma unroll
        for (int v = 0; v < 4; ++v) {
            int ch = (tid & 1) * 4 + v;
            cp_async16(stg + cdstA[v], Asrc + i * 64 + ch * 8);
        }
#pragma unroll
        for (int v = 0; v < 2; ++v) {
            int ch = (tid & 3) * 2 + v;
            cp_async16(stg + 32768u + cdstB[v], Bsrc + i * 64 + ch * 8);
        }
        cp_commit();
    };

    issue(0);
    if (NK > 1) issue(1);

    for (int i = 0; i < NK; ++i) {
        if (i + 2 < NK) cp_wait<1>(); else cp_wait<0>();
        __syncthreads();
        if (i + 2 < NK) issue(i + 2);

        uint32_t stg = sb + (uint32_t)(i % 3) * STAGE;
        const uint32_t Ab = stg, Bb = stg + 32768u;
#pragma unroll
        for (int ks = 0; ks < 4; ++ks) {
            uint32_t afr[2][4];
#pragma unroll
            for (int t2 = 0; t2 < 2; ++t2) {
                int row = wm * 32 + t2 * 16 + aro;
                uint32_t ad = Ab + (uint32_t)row * 128u
                            + (uint32_t)(((ks * 2 + aco) ^ (row & 7)) << 4);
                ldsm4(afr[t2], ad);
            }
            uint32_t bfr[4][4];
#pragma unroll
            for (int p = 0; p < 4; ++p) {
                int row = wn * 64 + p * 16 + bro;
                uint32_t bd = Bb + (uint32_t)row * 128u
                            + (uint32_t)(((ks * 2 + bco) ^ (row & 7)) << 4);
                ldsm4(bfr[p], bd);
            }
#pragma unroll
            for (int t2 = 0; t2 < 2; ++t2)
#pragma unroll
                for (int nt = 0; nt < 8; ++nt)
                    mma16816(acc[t2][nt], afr[t2], &bfr[nt >> 1][(nt & 1) * 2]);
        }
    }

    // ---- epilogue ----
    const int g = lane >> 2, tg = lane & 3;
    const float* brow = (MODE == 1)
        ? ((e < Em) ? (b1 + (size_t)e * Hm) : bs1)
        : ((e < Em) ? (b2 + (size_t)e * Dm) : bs2);

#pragma unroll
    for (int t2 = 0; t2 < 2; ++t2) {
        int row0 = wm * 32 + t2 * 16 + g;
        int row1 = row0 + 8;
        bool v0 = row0 < rows_valid, v1 = row1 < rows_valid;
#pragma unroll
        for (int nt = 0; nt < 8; ++nt) {
            int col = nbase + wn * 64 + nt * 8 + tg * 2;
            float bv0 = brow[col], bv1 = brow[col + 1];
            const float* c = acc[t2][nt];
            if (MODE == 1) {
                if (v0) {
                    __half2 h = __floats2half2_rn(gelu_exact(c[0] + bv0), gelu_exact(c[1] + bv1));
                    *(__half2*)(g_h + (size_t)(slot_base + row0) * Hm + col) = h;
                }
                if (v1) {
                    __half2 h = __floats2half2_rn(gelu_exact(c[2] + bv0), gelu_exact(c[3] + bv1));
                    *(__half2*)(g_h + (size_t)(slot_base + row1) * Hm + col) = h;
                }
            } else {
                if (v0) {
                    float2 o = make_float2(c[0] + bv0, c[1] + bv1);
                    *(float2*)(g_o2 + (size_t)(slot_base + row0) * Dm + col) = o;
                }
                if (v1) {
                    float2 o = make_float2(c[2] + bv0, c[3] + bv1);
                    *(float2*)(g_o2 + (size_t)(slot_base + row1) * Dm + col) = o;
                }
            }
        }
    }
}

// ================== kernel: combine (deterministic, no atomics) ==================
__global__ void k_combine(float* __restrict__ out) {
    int t = blockIdx.x;
    int d = threadIdx.x * 4;
    float4 sh = *(const float4*)(g_o2 + (size_t)t * Dm + d);
    int s0 = g_slot[2 * t], s1 = g_slot[2 * t + 1];
    float w0 = g_cw[2 * t], w1 = g_cw[2 * t + 1];
    float4 a = *(const float4*)(g_o2 + (size_t)s0 * Dm + d);
    float4 b = *(const float4*)(g_o2 + (size_t)s1 * Dm + d);
    float4 o;
    o.x = sh.x + w0 * a.x + w1 * b.x;
    o.y = sh.y + w0 * a.y + w1 * b.y;
    o.z = sh.z + w0 * a.z + w1 * b.z;
    o.w = sh.w + w0 * a.w + w1 * b.w;
    *(float4*)(out + (size_t)t * Dm + d) = o;
}

// ================== host launcher ==================
extern "C" void kernel_launch(void* const* d_in, const int* in_sizes, int n_in,
                              void* d_out, int out_size) {
    const float* x    = (const float*)d_in[0];
    const float* Wg   = (const float*)d_in[1];
    const float* bg   = (const float*)d_in[2];
    const float* bias = (const float*)d_in[3];
    const float* W1   = (const float*)d_in[4];
    const float* b1   = (const float*)d_in[5];
    const float* W2   = (const float*)d_in[6];
    const float* b2   = (const float*)d_in[7];
    const float* Ws1  = (const float*)d_in[8];
    const float* bs1  = (const float*)d_in[9];
    const float* Ws2  = (const float*)d_in[10];
    const float* bs2  = (const float*)d_in[11];
    float* out = (float*)d_out;
    (void)in_sizes; (void)n_in; (void)out_size;

    cudaFuncSetAttribute(k_gemm<1>, cudaFuncAttributeMaxDynamicSharedMemorySize, SMEM_BYTES);
    cudaFuncSetAttribute(k_gemm<2>, cudaFuncAttributeMaxDynamicSharedMemorySize, SMEM_BYTES);

    {
        long total4 = (2L * NG * HD) / 4;
        int blocks = (int)((total4 + 255) / 256);
        k_convert<<<blocks, 256>>>(W1, Ws1, W2, Ws2);   // launch 0
    }
    k_gating<<<Tm / 8, 256>>>(x, Wg, bg, bias);         // launch 1
    k_route<<<1, 1024>>>();                             // launch 2
    k_gemm<1><<<dim3(MAXTILES, Hm / 128), 512, SMEM_BYTES>>>(b1, bs1, b2, bs2); // launch 3 (profiled)
    k_gemm<2><<<dim3(MAXTILES, Dm / 128), 512, SMEM_BYTES>>>(b1, bs1, b2, bs2); // launch 4
    k_combine<<<Tm, 256>>>(out);                        // launch 5
}

// round 10
// speedup vs baseline: 1.0716x; 1.0716x over previous
#include <cuda_runtime.h>
#include <cuda_fp16.h>
#include <cstdint>

// ---------------- problem constants ----------------
constexpr int Dm = 1024;
constexpr int Hm = 4096;
constexpr int Em = 8;
constexpr int Tm = 2048;
constexpr int NG = 9;                    // 8 routed + shared at slot 8
constexpr int HD = Hm * Dm;              // 1<<22
constexpr int MAXROWS = Tm * 3;          // 6144
constexpr int PADROWS = MAXROWS + 128;
constexpr int MAXTILES = 64;
constexpr int TILE_M = 128;
constexpr int SMEM_BYTES = 98304;        // 3 stages x (16KB A + 16KB B)
constexpr int GEMM_GRID = 296;           // 2 CTAs/SM x 148 SMs, persistent

// ---------------- device scratch (static, no runtime alloc) ----------------
__device__ __half g_W1h[(size_t)NG * HD];
__device__ __half g_W2h[(size_t)NG * HD];
__device__ __half g_xh[(size_t)Tm * Dm];
__device__ __half g_h[(size_t)PADROWS * Hm];
__device__ float  g_o2[(size_t)PADROWS * Dm];
__device__ int    g_cnt9[NG];
__device__ int    g_off9[NG];
__device__ int    g_fill[Em];
__device__ int    g_tok[PADROWS];
__device__ int    g_slot[Tm * 2];
__device__ float  g_cw[Tm * 2];
__device__ int    g_topi[Tm * 2];
__device__ float  g_topw[Tm * 2];
__device__ int2   g_tiles[MAXTILES];
__device__ int    g_ntiles;

// ---------------- ptx helpers (sm_103-safe) -----
__device__ __forceinline__ uint32_t smem_u32(const void* p) {
    uint32_t a;
    asm("{ .reg .u64 t; cvta.to.shared.u64 t, %1; cvt.u32.u64 %0, t; }" : "=r"(a) : "l"(p));
    return a;
}
__device__ __forceinline__ void cp_async16(uint32_t saddr, const void* gaddr) {
    asm volatile("cp.async.cg.shared.global [%0], [%1], 16;" :: "r"(saddr), "l"(gaddr) : "memory");
}
__device__ __forceinline__ void cp_commit() {
    asm volatile("cp.async.commit_group;" ::: "memory");
}
template <int N>
__device__ __forceinline__ void cp_wait() {
    asm volatile("cp.async.wait_group %0;" :: "n"(N) : "memory");
}
__device__ __forceinline__ void ldsm4(uint32_t* r, uint32_t a) {
    asm volatile("ldmatrix.sync.aligned.m8n8.x4.shared.b16 {%0,%1,%2,%3}, [%4];"
        : "=r"(r[0]), "=r"(r[1]), "=r"(r[2]), "=r"(r[3]) : "r"(a));
}
__device__ __forceinline__ void mma16816(float* c, const uint32_t* a, const uint32_t* b) {
    asm volatile("mma.sync.aligned.m16n8k16.row.col.f32.f16.f16.f32 "
        "{%0,%1,%2,%3}, {%4,%5,%6,%7}, {%8,%9}, {%0,%1,%2,%3};"
        : "+f"(c[0]), "+f"(c[1]), "+f"(c[2]), "+f"(c[3])
        : "r"(a[0]), "r"(a[1]), "r"(a[2]), "r"(a[3]), "r"(b[0]), "r"(b[1]));
}
__device__ __forceinline__ float gelu_exact(float v) {
    return 0.5f * v * (1.0f + erff(v * 0.70710678118654752f));
}

// ================== kernel: fp32 -> fp16 weight conversion (+ counter zero) ==================
__global__ void k_convert(const float* __restrict__ W1, const float* __restrict__ Ws1,
                          const float* __restrict__ W2, const float* __restrict__ Ws2) {
    if (blockIdx.x == 0) {
        for (int i = threadIdx.x; i < PADROWS; i += blockDim.x) g_tok[i] = 0;
        if (threadIdx.x < Em) g_fill[threadIdx.x] = 0;
        if (threadIdx.x < NG) g_cnt9[threadIdx.x] = 0;
    }
    long i4 = (long)blockIdx.x * blockDim.x + threadIdx.x;
    long elem = i4 * 4;
    const long WPART = (long)NG * HD;
    const float* src;
    __half* dst;
    if (elem < WPART) {
        int e = (int)(elem >> 22);
        int off = (int)(elem & (HD - 1));
        src = (e < Em) ? (W1 + (size_t)e * HD + off) : (Ws1 + off);
        dst = g_W1h + elem;
    } else {
        long el = elem - WPART;
        if (el >= WPART) return;
        int e = (int)(el >> 22);
        int off = (int)(el & (HD - 1));
        src = (e < Em) ? (W2 + (size_t)e * HD + off) : (Ws2 + off);
        dst = g_W2h + el;
    }
    float4 v = *(const float4*)src;
    __half2 lo = __floats2half2_rn(v.x, v.y);
    __half2 hi = __floats2half2_rn(v.z, v.w);
    struct __align__(8) H4 { __half2 a, b; };
    *(H4*)dst = H4{lo, hi};
}

// ================== kernel: gating + x->fp16 ==================
__global__ void k_gating(const float* __restrict__ x, const float* __restrict__ Wg,
                         const float* __restrict__ bg, const float* __restrict__ bias) {
    int wid = threadIdx.x >> 5, lane = threadIdx.x & 31;
    int t = blockIdx.x * 8 + wid;
    float xr[32];
#pragma unroll
    for (int i = 0; i < 32; i++) xr[i] = x[(size_t)t * Dm + i * 32 + lane];
#pragma unroll
    for (int i = 0; i < 32; i++) g_xh[(size_t)t * Dm + i * 32 + lane] = __float2half_rn(xr[i]);
    float s[Em];
#pragma unroll
    for (int e = 0; e < Em; e++) {
        float acc = 0.f;
#pragma unroll
        for (int i = 0; i < 32; i++) acc = fmaf(xr[i], Wg[e * Dm + i * 32 + lane], acc);
#pragma unroll
        for (int off = 16; off >= 1; off >>= 1) acc += __shfl_xor_sync(0xFFFFFFFFu, acc, off);
        s[e] = 1.f / (1.f + expf(-(acc + bg[e] + bias[e])));
    }
    if (lane == 0) {
        int i0 = 0;
#pragma unroll
        for (int e = 1; e < Em; e++) if (s[e] > s[i0]) i0 = e;
        int i1 = -1;
#pragma unroll
        for (int e = 0; e < Em; e++) if (e != i0 && (i1 < 0 || s[e] > s[i1])) i1 = e;
        g_topi[2 * t] = i0;     g_topw[2 * t] = s[i0];
        g_topi[2 * t + 1] = i1; g_topw[2 * t + 1] = s[i1];
        atomicAdd(&g_cnt9[i0], 1);
        atomicAdd(&g_cnt9[i1], 1);
    }
}

// ================== kernel: routing (offsets + tile table + scatter), 1 block ==================
__global__ __launch_bounds__(1024) void k_route() {
    if (threadIdx.x == 0) {
        g_cnt9[8] = Tm;
        g_off9[8] = 0;
        int nt = 0;
        for (int rs = 0; rs < Tm; rs += TILE_M) g_tiles[nt++] = make_int2(8, rs);
        int p = Tm;
        for (int e = 0; e < Em; e++) {
            g_off9[e] = p;
            p += g_cnt9[e];
            for (int rs = 0; rs < g_cnt9[e]; rs += TILE_M) g_tiles[nt++] = make_int2(e, rs);
        }
        g_ntiles = nt;
    }
    __syncthreads();
#pragma unroll
    for (int r = 0; r < 2; ++r) {
        int t = threadIdx.x + r * 1024;
        g_tok[t] = t; // shared slots occupy [0, Tm)
#pragma unroll
        for (int k = 0; k < 2; k++) {
            int e = g_topi[2 * t + k];
            float w = g_topw[2 * t + k];
            int pos = atomicAdd(&g_fill[e], 1);
            int slot = g_off9[e] + pos;
            g_tok[slot] = t;
            g_slot[2 * t + k] = slot;
            g_cw[2 * t + k] = w;
        }
    }
}

// ================== grouped GEMM, persistent CTAs, 128x128 tile, HMMA f32-acc ==================
// 296 persistent CTAs (2/SM), 256 threads = 8 warps in 4(m) x 2(n); warp tile 32x64.
// Work item = m-tile * NB + n-block, grid-strided -> no wave quantization, no dead CTAs.
// 3-stage cp.async pipeline, one __syncthreads per K=64 chunk.
// MODE 1: h = gelu(x @ W1^T + b1) -> g_h (fp16), K = 1024
// MODE 2: o2 = h @ W2^T + b2      -> g_o2 (fp32), K = 4096
template <int MODE>
__global__ __launch_bounds__(256, 2) void k_gemm(
    const float* __restrict__ b1, const float* __restrict__ bs1,
    const float* __restrict__ b2, const float* __restrict__ bs2)
{
    extern __shared__ char smem[];
    const int tid = threadIdx.x;
    const int lane = tid & 31, wid = tid >> 5;
    const int wm = wid >> 1, wn = wid & 1;

    constexpr int K = (MODE == 1) ? Dm : Hm;
    constexpr int NK = K / 64;
    constexpr int NB = ((MODE == 1) ? Hm : Dm) / 128;

    uint32_t sb = smem_u32(smem);

    // ---- invariant per-thread copy/ldsm mappings ----
    const int crow = tid >> 1;
    uint32_t cdst[4];
#pragma unroll
    for (int v = 0; v < 4; ++v) {
        int ch = (tid & 1) * 4 + v;
        cdst[v] = (uint32_t)crow * 128u + (uint32_t)((ch ^ (crow & 7)) << 4);
    }
    const int m4 = lane >> 3;
    const int aro = ((m4 & 1) << 3) + (lane & 7);
    const int aco = m4 >> 1;
    const int bro = ((m4 >> 1) << 3) + (lane & 7);
    const int bco = m4 & 1;
    const int g = lane >> 2, tg = lane & 3;

    const int ntiles = g_ntiles;
    const int total = ntiles * NB;

    for (int item = blockIdx.x; item < total; item += GEMM_GRID) {
        const int mt = item / NB;
        const int nbase = (item - mt * NB) * 128;
        int2 tl = g_tiles[mt];
        const int e = tl.x, rs = tl.y;
        const int rows_valid = g_cnt9[e] - rs;
        const int slot_base = g_off9[e] + rs;

        const __half* Asrc;
        if (MODE == 1) {
            int tok = g_tok[slot_base + crow];
            Asrc = g_xh + (size_t)tok * Dm;
        } else {
            Asrc = g_h + (size_t)(slot_base + crow) * Hm;
        }
        const __half* Bsrc = ((MODE == 1) ? g_W1h : g_W2h)
                             + (size_t)e * HD + (size_t)(nbase + crow) * K;

        float acc[2][8][4];
#pragma unroll
        for (int a = 0; a < 2; ++a)
#pragma unroll
            for (int b = 0; b < 8; ++b)
#pragma unroll
                for (int c = 0; c < 4; ++c) acc[a][b][c] = 0.f;

        auto issue = [&](int i) {
            uint32_t stg = sb + (uint32_t)(i % 3) * 32768u;
#pragma unroll
            for (int v = 0; v < 4; ++v) {
                int ch = (tid & 1) * 4 + v;
                cp_async16(stg + cdst[v], Asrc + i * 64 + ch * 8);
                cp_async16(stg + 16384u + cdst[v], Bsrc + i * 64 + ch * 8);
            }
            cp_commit();
        };

        issue(0);
        issue(1);

        for (int i = 0; i < NK; ++i) {
            if (i + 2 < NK) cp_wait<1>(); else cp_wait<0>();
            __syncthreads();
            if (i + 2 < NK) issue(i + 2);

            uint32_t stg = sb + (uint32_t)(i % 3) * 32768u;
            const uint32_t Ab = stg, Bb = stg + 16384u;
#pragma unroll
            for (int ks = 0; ks < 4; ++ks) {
                uint32_t afr[2][4];
#pragma unroll
                for (int t2 = 0; t2 < 2; ++t2) {
                    int row = wm * 32 + t2 * 16 + aro;
                    uint32_t ad = Ab + (uint32_t)row * 128u
                                + (uint32_t)(((ks * 2 + aco) ^ (row & 7)) << 4);
                    ldsm4(afr[t2], ad);
                }
                uint32_t bfr[4][4];
#pragma unroll
                for (int p = 0; p < 4; ++p) {
                    int row = wn * 64 + p * 16 + bro;
                    uint32_t bd = Bb + (uint32_t)row * 128u
                                + (uint32_t)(((ks * 2 + bco) ^ (row & 7)) << 4);
                    ldsm4(bfr[p], bd);
                }
#pragma unroll
                for (int t2 = 0; t2 < 2; ++t2)
#pragma unroll
                    for (int nt = 0; nt < 8; ++nt)
                        mma16816(acc[t2][nt], afr[t2], &bfr[nt >> 1][(nt & 1) * 2]);
            }
        }

        // ---- epilogue ----
        const float* brow = (MODE == 1)
            ? ((e < Em) ? (b1 + (size_t)e * Hm) : bs1)
            : ((e < Em) ? (b2 + (size_t)e * Dm) : bs2);

#pragma unroll
        for (int t2 = 0; t2 < 2; ++t2) {
            int row0 = wm * 32 + t2 * 16 + g;
            int row1 = row0 + 8;
            bool v0 = row0 < rows_valid, v1 = row1 < rows_valid;
#pragma unroll
            for (int nt = 0; nt < 8; ++nt) {
                int col = nbase + wn * 64 + nt * 8 + tg * 2;
                float bv0 = brow[col], bv1 = brow[col + 1];
                const float* c = acc[t2][nt];
                if (MODE == 1) {
                    if (v0) {
                        __half2 h = __floats2half2_rn(gelu_exact(c[0] + bv0), gelu_exact(c[1] + bv1));
                        *(__half2*)(g_h + (size_t)(slot_base + row0) * Hm + col) = h;
                    }
                    if (v1) {
                        __half2 h = __floats2half2_rn(gelu_exact(c[2] + bv0), gelu_exact(c[3] + bv1));
                        *(__half2*)(g_h + (size_t)(slot_base + row1) * Hm + col) = h;
                    }
                } else {
                    if (v0) {
                        float2 o = make_float2(c[0] + bv0, c[1] + bv1);
                        *(float2*)(g_o2 + (size_t)(slot_base + row0) * Dm + col) = o;
                    }
                    if (v1) {
                        float2 o = make_float2(c[2] + bv0, c[3] + bv1);
                        *(float2*)(g_o2 + (size_t)(slot_base + row1) * Dm + col) = o;
                    }
                }
            }
        }
        __syncthreads();   // protect smem stages before next item's cp.async
    }
}

// ================== kernel: combine (deterministic, no atomics) ==================
__global__ void k_combine(float* __restrict__ out) {
    int t = blockIdx.x;
    int d = threadIdx.x * 4;
    float4 sh = *(const float4*)(g_o2 + (size_t)t * Dm + d);
    int s0 = g_slot[2 * t], s1 = g_slot[2 * t + 1];
    float w0 = g_cw[2 * t], w1 = g_cw[2 * t + 1];
    float4 a = *(const float4*)(g_o2 + (size_t)s0 * Dm + d);
    float4 b = *(const float4*)(g_o2 + (size_t)s1 * Dm + d);
    float4 o;
    o.x = sh.x + w0 * a.x + w1 * b.x;
    o.y = sh.y + w0 * a.y + w1 * b.y;
    o.z = sh.z + w0 * a.z + w1 * b.z;
    o.w = sh.w + w0 * a.w + w1 * b.w;
    *(float4*)(out + (size_t)t * Dm + d) = o;
}

// ================== host launcher ==================
extern "C" void kernel_launch(void* const* d_in, const int* in_sizes, int n_in,
                              void* d_out, int out_size) {
    const float* x    = (const float*)d_in[0];
    const float* Wg   = (const float*)d_in[1];
    const float* bg   = (const float*)d_in[2];
    const float* bias = (const float*)d_in[3];
    const float* W1   = (const float*)d_in[4];
    const float* b1   = (const float*)d_in[5];
    const float* W2   = (const float*)d_in[6];
    const float* b2   = (const float*)d_in[7];
    const float* Ws1  = (const float*)d_in[8];
    const float* bs1  = (const float*)d_in[9];
    const float* Ws2  = (const float*)d_in[10];
    const float* bs2  = (const float*)d_in[11];
    float* out = (float*)d_out;
    (void)in_sizes; (void)n_in; (void)out_size;

    cudaFuncSetAttribute(k_gemm<1>, cudaFuncAttributeMaxDynamicSharedMemorySize, SMEM_BYTES);
    cudaFuncSetAttribute(k_gemm<2>, cudaFuncAttributeMaxDynamicSharedMemorySize, SMEM_BYTES);

    {
        long total4 = (2L * NG * HD) / 4;
        int blocks = (int)((total4 + 255) / 256);
        k_convert<<<blocks, 256>>>(W1, Ws1, W2, Ws2);   // launch 0
    }
    k_gating<<<Tm / 8, 256>>>(x, Wg, bg, bias);         // launch 1
    k_route<<<1, 1024>>>();                             // launch 2
    k_gemm<1><<<GEMM_GRID, 256, SMEM_BYTES>>>(b1, bs1, b2, bs2); // launch 3 (profiled)
    k_gemm<2><<<GEMM_GRID, 256, SMEM_BYTES>>>(b1, bs1, b2, bs2); // launch 4
    k_combine<<<Tm, 256>>>(out);                        // launch 5
}

// round 11
// speedup vs baseline: 1.1264x; 1.0511x over previous
#include <cuda_runtime.h>
#include <cuda_fp16.h>
#include <cstdint>

// ---------------- problem constants ----------------
constexpr int Dm = 1024;
constexpr int Hm = 4096;
constexpr int Em = 8;
constexpr int Tm = 2048;
constexpr int NG = 9;                    // 8 routed + shared at slot 8
constexpr int HD = Hm * Dm;              // 1<<22
constexpr int MAXROWS = Tm * 3;          // 6144
constexpr int PADROWS = MAXROWS + 128;
constexpr int MAXTILES = 64;
constexpr int TILE_M = 128;
constexpr int SMEM_BYTES = 98304;        // 3 stages x (16KB A + 16KB B)

// ---------------- device scratch (static, no runtime alloc) ----------------
__device__ __half g_W1h[(size_t)NG * HD];
__device__ __half g_W2h[(size_t)NG * HD];
__device__ __half g_xh[(size_t)Tm * Dm];
__device__ __half g_h[(size_t)PADROWS * Hm];
__device__ float  g_o2[(size_t)PADROWS * Dm];
__device__ int    g_cnt9[NG];
__device__ int    g_off9[NG];
__device__ int    g_fill[Em];
__device__ int    g_tok[PADROWS];
__device__ int    g_slot[Tm * 2];
__device__ float  g_cw[Tm * 2];
__device__ int    g_topi[Tm * 2];
__device__ float  g_topw[Tm * 2];
__device__ int2   g_tiles[MAXTILES];
__device__ int    g_ntiles;

// ---------------- ptx helpers (sm_103-safe) -----
__device__ __forceinline__ uint32_t smem_u32(const void* p) {
    uint32_t a;
    asm("{ .reg .u64 t; cvta.to.shared.u64 t, %1; cvt.u32.u64 %0, t; }" : "=r"(a) : "l"(p));
    return a;
}
__device__ __forceinline__ void cp_async16(uint32_t saddr, const void* gaddr) {
    asm volatile("cp.async.cg.shared.global [%0], [%1], 16;" :: "r"(saddr), "l"(gaddr) : "memory");
}
__device__ __forceinline__ void cp_commit() {
    asm volatile("cp.async.commit_group;" ::: "memory");
}
template <int N>
__device__ __forceinline__ void cp_wait() {
    asm volatile("cp.async.wait_group %0;" :: "n"(N) : "memory");
}
__device__ __forceinline__ void ldsm4(uint32_t* r, uint32_t a) {
    asm volatile("ldmatrix.sync.aligned.m8n8.x4.shared.b16 {%0,%1,%2,%3}, [%4];"
        : "=r"(r[0]), "=r"(r[1]), "=r"(r[2]), "=r"(r[3]) : "r"(a));
}
__device__ __forceinline__ void mma16816(float* c, const uint32_t* a, const uint32_t* b) {
    asm volatile("mma.sync.aligned.m16n8k16.row.col.f32.f16.f16.f32 "
        "{%0,%1,%2,%3}, {%4,%5,%6,%7}, {%8,%9}, {%0,%1,%2,%3};"
        : "+f"(c[0]), "+f"(c[1]), "+f"(c[2]), "+f"(c[3])
        : "r"(a[0]), "r"(a[1]), "r"(a[2]), "r"(a[3]), "r"(b[0]), "r"(b[1]));
}
__device__ __forceinline__ float gelu_exact(float v) {
    return 0.5f * v * (1.0f + erff(v * 0.70710678118654752f));
}

// ================== conversion kernels (fp32 -> fp16), split per weight family ==================
__global__ void k_convert1(const float* __restrict__ W1, const float* __restrict__ Ws1) {
    long elem = ((long)blockIdx.x * blockDim.x + threadIdx.x) * 4;
    if (elem >= (long)NG * HD) return;
    int e = (int)(elem >> 22);
    int off = (int)(elem & (HD - 1));
    const float* src = (e < Em) ? (W1 + (size_t)e * HD + off) : (Ws1 + off);
    float4 v = *(const float4*)src;
    __half2 lo = __floats2half2_rn(v.x, v.y);
    __half2 hi = __floats2half2_rn(v.z, v.w);
    struct __align__(8) H4 { __half2 a, b; };
    *(H4*)(g_W1h + elem) = H4{lo, hi};
}
__global__ void k_convert2(const float* __restrict__ W2, const float* __restrict__ Ws2) {
    long elem = ((long)blockIdx.x * blockDim.x + threadIdx.x) * 4;
    if (elem >= (long)NG * HD) return;
    int e = (int)(elem >> 22);
    int off = (int)(elem & (HD - 1));
    const float* src = (e < Em) ? (W2 + (size_t)e * HD + off) : (Ws2 + off);
    float4 v = *(const float4*)src;
    __half2 lo = __floats2half2_rn(v.x, v.y);
    __half2 hi = __floats2half2_rn(v.z, v.w);
    struct __align__(8) H4 { __half2 a, b; };
    *(H4*)(g_W2h + elem) = H4{lo, hi};
}

// ================== kernel: zero counters + token table ==================
__global__ void k_zero() {
    int i = blockIdx.x * blockDim.x + threadIdx.x;
    if (i < PADROWS) g_tok[i] = 0;
    if (i < Em) g_fill[i] = 0;
    if (i < NG) g_cnt9[i] = 0;
}

// ================== kernel: gating + x->fp16 ==================
__global__ void k_gating(const float* __restrict__ x, const float* __restrict__ Wg,
                         const float* __restrict__ bg, const float* __restrict__ bias) {
    int wid = threadIdx.x >> 5, lane = threadIdx.x & 31;
    int t = blockIdx.x * 8 + wid;
    float xr[32];
#pragma unroll
    for (int i = 0; i < 32; i++) xr[i] = x[(size_t)t * Dm + i * 32 + lane];
#pragma unroll
    for (int i = 0; i < 32; i++) g_xh[(size_t)t * Dm + i * 32 + lane] = __float2half_rn(xr[i]);
    float s[Em];
#pragma unroll
    for (int e = 0; e < Em; e++) {
        float acc = 0.f;
#pragma unroll
        for (int i = 0; i < 32; i++) acc = fmaf(xr[i], Wg[e * Dm + i * 32 + lane], acc);
#pragma unroll
        for (int off = 16; off >= 1; off >>= 1) acc += __shfl_xor_sync(0xFFFFFFFFu, acc, off);
        s[e] = 1.f / (1.f + expf(-(acc + bg[e] + bias[e])));
    }
    if (lane == 0) {
        int i0 = 0;
#pragma unroll
        for (int e = 1; e < Em; e++) if (s[e] > s[i0]) i0 = e;
        int i1 = -1;
#pragma unroll
        for (int e = 0; e < Em; e++) if (e != i0 && (i1 < 0 || s[e] > s[i1])) i1 = e;
        g_topi[2 * t] = i0;     g_topw[2 * t] = s[i0];
        g_topi[2 * t + 1] = i1; g_topw[2 * t + 1] = s[i1];
        atomicAdd(&g_cnt9[i0], 1);
        atomicAdd(&g_cnt9[i1], 1);
    }
}

// ================== kernel: routing (offsets + tile table + scatter), 1 block ==================
__global__ __launch_bounds__(1024) void k_route() {
    if (threadIdx.x == 0) {
        g_cnt9[8] = Tm;
        g_off9[8] = 0;
        int nt = 0;
        for (int rs = 0; rs < Tm; rs += TILE_M) g_tiles[nt++] = make_int2(8, rs);
        int p = Tm;
        for (int e = 0; e < Em; e++) {
            g_off9[e] = p;
            p += g_cnt9[e];
            for (int rs = 0; rs < g_cnt9[e]; rs += TILE_M) g_tiles[nt++] = make_int2(e, rs);
        }
        g_ntiles = nt;
    }
    __syncthreads();
#pragma unroll
    for (int r = 0; r < 2; ++r) {
        int t = threadIdx.x + r * 1024;
        g_tok[t] = t; // shared slots occupy [0, Tm)
#pragma unroll
        for (int k = 0; k < 2; k++) {
            int e = g_topi[2 * t + k];
            float w = g_topw[2 * t + k];
            int pos = atomicAdd(&g_fill[e], 1);
            int slot = g_off9[e] + pos;
            g_tok[slot] = t;
            g_slot[2 * t + k] = slot;
            g_cw[2 * t + k] = w;
        }
    }
}

// ================== grouped GEMM, 128x128 tile, HMMA m16n8k16 f32-acc (R8 config) ==================
// 256 threads = 8 warps in 4(m) x 2(n); each warp computes 32x64.
// 3-stage cp.async pipeline, one __syncthreads per K=64 chunk, 2 CTAs/SM.
// MODE 1: h = gelu(x @ W1^T + b1) -> g_h (fp16), K = 1024
// MODE 2: o2 = h @ W2^T + b2      -> g_o2 (fp32), K = 4096
template <int MODE>
__global__ __launch_bounds__(256, 2) void k_gemm(
    const float* __restrict__ b1, const float* __restrict__ bs1,
    const float* __restrict__ b2, const float* __restrict__ bs2)
{
    extern __shared__ char smem[];
    const int tid = threadIdx.x;
    const int lane = tid & 31, wid = tid >> 5;
    const int wm = wid >> 1, wn = wid & 1;

    int mt = blockIdx.x;
    if (mt >= g_ntiles) return;
    int2 tl = g_tiles[mt];
    const int e = tl.x, rs = tl.y;
    const int rows_valid = g_cnt9[e] - rs;
    const int slot_base = g_off9[e] + rs;
    const int nbase = blockIdx.y * 128;

    constexpr int K = (MODE == 1) ? Dm : Hm;
    constexpr int NK = K / 64;

    uint32_t sb = smem_u32(smem);

    const int crow = tid >> 1;
    const __half* Asrc;
    if (MODE == 1) {
        int tok = g_tok[slot_base + crow];
        Asrc = g_xh + (size_t)tok * Dm;
    } else {
        Asrc = g_h + (size_t)(slot_base + crow) * Hm;
    }
    const __half* Bsrc = ((MODE == 1) ? g_W1h : g_W2h)
                         + (size_t)e * HD + (size_t)(nbase + crow) * K;
    uint32_t cdst[4];
#pragma unroll
    for (int v = 0; v < 4; ++v) {
        int ch = (tid & 1) * 4 + v;
        cdst[v] = (uint32_t)crow * 128u + (uint32_t)((ch ^ (crow & 7)) << 4);
    }

    const int m4 = lane >> 3;
    const int aro = ((m4 & 1) << 3) + (lane & 7);
    const int aco = m4 >> 1;
    const int bro = ((m4 >> 1) << 3) + (lane & 7);
    const int bco = m4 & 1;

    float acc[2][8][4];
#pragma unroll
    for (int a = 0; a < 2; ++a)
#pragma unroll
        for (int b = 0; b < 8; ++b)
#pragma unroll
            for (int c = 0; c < 4; ++c) acc[a][b][c] = 0.f;

    auto issue = [&](int i) {
        uint32_t stg = sb + (uint32_t)(i % 3) * 32768u;
#pragma unroll
        for (int v = 0; v < 4; ++v) {
            int ch = (tid & 1) * 4 + v;
            cp_async16(stg + cdst[v], Asrc + i * 64 + ch * 8);
            cp_async16(stg + 16384u + cdst[v], Bsrc + i * 64 + ch * 8);
        }
        cp_commit();
    };

    issue(0);
    issue(1);

    for (int i = 0; i < NK; ++i) {
        if (i + 2 < NK) cp_wait<1>(); else cp_wait<0>();
        __syncthreads();
        if (i + 2 < NK) issue(i + 2);

        uint32_t stg = sb + (uint32_t)(i % 3) * 32768u;
        const uint32_t Ab = stg, Bb = stg + 16384u;
#pragma unroll
        for (int ks = 0; ks < 4; ++ks) {
            uint32_t afr[2][4];
#pragma unroll
            for (int t2 = 0; t2 < 2; ++t2) {
                int row = wm * 32 + t2 * 16 + aro;
                uint32_t ad = Ab + (uint32_t)row * 128u
                            + (uint32_t)(((ks * 2 + aco) ^ (row & 7)) << 4);
                ldsm4(afr[t2], ad);
            }
            uint32_t bfr[4][4];
#pragma unroll
            for (int p = 0; p < 4; ++p) {
                int row = wn * 64 + p * 16 + bro;
                uint32_t bd = Bb + (uint32_t)row * 128u
                            + (uint32_t)(((ks * 2 + bco) ^ (row & 7)) << 4);
                ldsm4(bfr[p], bd);
            }
#pragma unroll
            for (int t2 = 0; t2 < 2; ++t2)
#pragma unroll
                for (int nt = 0; nt < 8; ++nt)
                    mma16816(acc[t2][nt], afr[t2], &bfr[nt >> 1][(nt & 1) * 2]);
        }
    }

    // ---- epilogue ----
    const int g = lane >> 2, tg = lane & 3;
    const float* brow = (MODE == 1)
        ? ((e < Em) ? (b1 + (size_t)e * Hm) : bs1)
        : ((e < Em) ? (b2 + (size_t)e * Dm) : bs2);

#pragma unroll
    for (int t2 = 0; t2 < 2; ++t2) {
        int row0 = wm * 32 + t2 * 16 + g;
        int row1 = row0 + 8;
        bool v0 = row0 < rows_valid, v1 = row1 < rows_valid;
#pragma unroll
        for (int nt = 0; nt < 8; ++nt) {
            int col = nbase + wn * 64 + nt * 8 + tg * 2;
            float bv0 = brow[col], bv1 = brow[col + 1];
            const float* c = acc[t2][nt];
            if (MODE == 1) {
                if (v0) {
                    __half2 h = __floats2half2_rn(gelu_exact(c[0] + bv0), gelu_exact(c[1] + bv1));
                    *(__half2*)(g_h + (size_t)(slot_base + row0) * Hm + col) = h;
                }
                if (v1) {
                    __half2 h = __floats2half2_rn(gelu_exact(c[2] + bv0), gelu_exact(c[3] + bv1));
                    *(__half2*)(g_h + (size_t)(slot_base + row1) * Hm + col) = h;
                }
            } else {
                if (v0) {
                    float2 o = make_float2(c[0] + bv0, c[1] + bv1);
                    *(float2*)(g_o2 + (size_t)(slot_base + row0) * Dm + col) = o;
                }
                if (v1) {
                    float2 o = make_float2(c[2] + bv0, c[3] + bv1);
                    *(float2*)(g_o2 + (size_t)(slot_base + row1) * Dm + col) = o;
                }
            }
        }
    }
}

// ================== kernel: combine (deterministic, no atomics) ==================
__global__ void k_combine(float* __restrict__ out) {
    int t = blockIdx.x;
    int d = threadIdx.x * 4;
    float4 sh = *(const float4*)(g_o2 + (size_t)t * Dm + d);
    int s0 = g_slot[2 * t], s1 = g_slot[2 * t + 1];
    float w0 = g_cw[2 * t], w1 = g_cw[2 * t + 1];
    float4 a = *(const float4*)(g_o2 + (size_t)s0 * Dm + d);
    float4 b = *(const float4*)(g_o2 + (size_t)s1 * Dm + d);
    float4 o;
    o.x = sh.x + w0 * a.x + w1 * b.x;
    o.y = sh.y + w0 * a.y + w1 * b.y;
    o.z = sh.z + w0 * a.z + w1 * b.z;
    o.w = sh.w + w0 * a.w + w1 * b.w;
    *(float4*)(out + (size_t)t * Dm + d) = o;
}

// ================== host launcher (multi-stream fork for weight conversion) ==================
extern "C" void kernel_launch(void* const* d_in, const int* in_sizes, int n_in,
                              void* d_out, int out_size) {
    const float* x    = (const float*)d_in[0];
    const float* Wg   = (const float*)d_in[1];
    const float* bg   = (const float*)d_in[2];
    const float* bias = (const float*)d_in[3];
    const float* W1   = (const float*)d_in[4];
    const float* b1   = (const float*)d_in[5];
    const float* W2   = (const float*)d_in[6];
    const float* b2   = (const float*)d_in[7];
    const float* Ws1  = (const float*)d_in[8];
    const float* bs1  = (const float*)d_in[9];
    const float* Ws2  = (const float*)d_in[10];
    const float* bs2  = (const float*)d_in[11];
    float* out = (float*)d_out;
    (void)in_sizes; (void)n_in; (void)out_size;

    // host-side resources, created once (no device memory involved)
    static cudaStream_t s1 = nullptr, s2 = nullptr;
    static cudaEvent_t evA = nullptr, ev1 = nullptr, ev2 = nullptr;
    if (s1 == nullptr) {
        cudaStreamCreateWithFlags(&s1, cudaStreamNonBlocking);
        cudaStreamCreateWithFlags(&s2, cudaStreamNonBlocking);
        cudaEventCreateWithFlags(&evA, cudaEventDisableTiming);
        cudaEventCreateWithFlags(&ev1, cudaEventDisableTiming);
        cudaEventCreateWithFlags(&ev2, cudaEventDisableTiming);
        cudaFuncSetAttribute(k_gemm<1>, cudaFuncAttributeMaxDynamicSharedMemorySize, SMEM_BYTES);
        cudaFuncSetAttribute(k_gemm<2>, cudaFuncAttributeMaxDynamicSharedMemorySize, SMEM_BYTES);
    }

    const int cvt_blocks = (int)(((long)NG * HD / 4 + 255) / 256);

    // fork: convert1 (needed by GEMM1) and convert2 (needed only by GEMM2) on side streams
    cudaEventRecord(evA, 0);
    cudaStreamWaitEvent(s1, evA, 0);
    k_convert1<<<cvt_blocks, 256, 0, s1>>>(W1, Ws1);
    cudaEventRecord(ev1, s1);
    cudaStreamWaitEvent(s2, evA, 0);
    k_convert2<<<cvt_blocks, 256, 0, s2>>>(W2, Ws2);
    cudaEventRecord(ev2, s2);

    // main stream: routing pipeline (independent of weight conversion)
    k_zero<<<(PADROWS + 255) / 256, 256>>>();
    k_gating<<<Tm / 8, 256>>>(x, Wg, bg, bias);
    k_route<<<1, 1024>>>();

    // GEMM1 needs convert1
    cudaStreamWaitEvent(0, ev1, 0);
    k_gemm<1><<<dim3(MAXTILES, Hm / 128), 256, SMEM_BYTES>>>(b1, bs1, b2, bs2);  // launch idx 5 (profiled)
    // GEMM2 needs GEMM1 + convert2 (convert2 hidden under GEMM1)
    cudaStreamWaitEvent(0, ev2, 0);
    k_gemm<2><<<dim3(MAXTILES, Dm / 128), 256, SMEM_BYTES>>>(b1, bs1, b2, bs2);
    k_combine<<<Tm, 256>>>(out);
}

// round 12
// speedup vs baseline: 1.1522x; 1.0229x over previous
#include <cuda_runtime.h>
#include <cuda_fp16.h>
#include <cstdint>

// ---------------- problem constants ----------------
constexpr int Dm = 1024;
constexpr int Hm = 4096;
constexpr int Em = 8;
constexpr int Tm = 2048;
constexpr int NG = 9;                    // 8 routed + shared at slot 8
constexpr int HD = Hm * Dm;              // 1<<22
constexpr int MAXROWS = Tm * 3;          // 6144
constexpr int PADROWS = MAXROWS + 128;
constexpr int MAXTILES = 64;
constexpr int TILE_M = 128;
constexpr int SMEM_BYTES = 98304;        // 3 stages x (16KB A + 16KB B)

// ---------------- device scratch (static, no runtime alloc) ----------------
__device__ __half g_W1h[(size_t)NG * HD];
__device__ __half g_W2h[(size_t)NG * HD];
__device__ __half g_xh[(size_t)Tm * Dm];
__device__ __half g_h[(size_t)PADROWS * Hm];
__device__ float  g_o2[(size_t)PADROWS * Dm];
__device__ int    g_cnt9[NG];
__device__ int    g_off9[NG];
__device__ int    g_fill[Em];
__device__ int    g_tok[PADROWS];
__device__ int    g_slot[Tm * 2];
__device__ float  g_cw[Tm * 2];
__device__ int    g_topi[Tm * 2];
__device__ float  g_topw[Tm * 2];
__device__ int2   g_tiles[MAXTILES];
__device__ int    g_ntiles;

// ---------------- ptx helpers (sm_103-safe) -----
__device__ __forceinline__ uint32_t smem_u32(const void* p) {
    uint32_t a;
    asm("{ .reg .u64 t; cvta.to.shared.u64 t, %1; cvt.u32.u64 %0, t; }" : "=r"(a) : "l"(p));
    return a;
}
__device__ __forceinline__ void cp_async16(uint32_t saddr, const void* gaddr) {
    asm volatile("cp.async.cg.shared.global [%0], [%1], 16;" :: "r"(saddr), "l"(gaddr) : "memory");
}
__device__ __forceinline__ void cp_commit() {
    asm volatile("cp.async.commit_group;" ::: "memory");
}
template <int N>
__device__ __forceinline__ void cp_wait() {
    asm volatile("cp.async.wait_group %0;" :: "n"(N) : "memory");
}
__device__ __forceinline__ void ldsm4(uint32_t* r, uint32_t a) {
    asm volatile("ldmatrix.sync.aligned.m8n8.x4.shared.b16 {%0,%1,%2,%3}, [%4];"
        : "=r"(r[0]), "=r"(r[1]), "=r"(r[2]), "=r"(r[3]) : "r"(a));
}
__device__ __forceinline__ void mma16816(float* c, const uint32_t* a, const uint32_t* b) {
    asm volatile("mma.sync.aligned.m16n8k16.row.col.f32.f16.f16.f32 "
        "{%0,%1,%2,%3}, {%4,%5,%6,%7}, {%8,%9}, {%0,%1,%2,%3};"
        : "+f"(c[0]), "+f"(c[1]), "+f"(c[2]), "+f"(c[3])
        : "r"(a[0]), "r"(a[1]), "r"(a[2]), "r"(a[3]), "r"(b[0]), "r"(b[1]));
}
__device__ __forceinline__ float gelu_exact(float v) {
    return 0.5f * v * (1.0f + erff(v * 0.70710678118654752f));
}

// ================== conversion kernels (fp32 -> fp16), split per weight family ==================
__global__ void k_convert1(const float* __restrict__ W1, const float* __restrict__ Ws1) {
    long elem = ((long)blockIdx.x * blockDim.x + threadIdx.x) * 4;
    if (elem >= (long)NG * HD) return;
    int e = (int)(elem >> 22);
    int off = (int)(elem & (HD - 1));
    const float* src = (e < Em) ? (W1 + (size_t)e * HD + off) : (Ws1 + off);
    float4 v = *(const float4*)src;
    __half2 lo = __floats2half2_rn(v.x, v.y);
    __half2 hi = __floats2half2_rn(v.z, v.w);
    struct __align__(8) H4 { __half2 a, b; };
    *(H4*)(g_W1h + elem) = H4{lo, hi};
}
__global__ void k_convert2(const float* __restrict__ W2, const float* __restrict__ Ws2) {
    long elem = ((long)blockIdx.x * blockDim.x + threadIdx.x) * 4;
    if (elem >= (long)NG * HD) return;
    int e = (int)(elem >> 22);
    int off = (int)(elem & (HD - 1));
    const float* src = (e < Em) ? (W2 + (size_t)e * HD + off) : (Ws2 + off);
    float4 v = *(const float4*)src;
    __half2 lo = __floats2half2_rn(v.x, v.y);
    __half2 hi = __floats2half2_rn(v.z, v.w);
    struct __align__(8) H4 { __half2 a, b; };
    *(H4*)(g_W2h + elem) = H4{lo, hi};
}

// ================== kernel: zero counters + token table ==================
__global__ void k_zero() {
    int i = blockIdx.x * blockDim.x + threadIdx.x;
    if (i < PADROWS) g_tok[i] = 0;
    if (i < Em) g_fill[i] = 0;
    if (i < NG) g_cnt9[i] = 0;
}

// ================== kernel: gating + x->fp16 ==================
__global__ void k_gating(const float* __restrict__ x, const float* __restrict__ Wg,
                         const float* __restrict__ bg, const float* __restrict__ bias) {
    int wid = threadIdx.x >> 5, lane = threadIdx.x & 31;
    int t = blockIdx.x * 8 + wid;
    float xr[32];
#pragma unroll
    for (int i = 0; i < 32; i++) xr[i] = x[(size_t)t * Dm + i * 32 + lane];
#pragma unroll
    for (int i = 0; i < 32; i++) g_xh[(size_t)t * Dm + i * 32 + lane] = __float2half_rn(xr[i]);
    float s[Em];
#pragma unroll
    for (int e = 0; e < Em; e++) {
        float acc = 0.f;
#pragma unroll
        for (int i = 0; i < 32; i++) acc = fmaf(xr[i], Wg[e * Dm + i * 32 + lane], acc);
#pragma unroll
        for (int off = 16; off >= 1; off >>= 1) acc += __shfl_xor_sync(0xFFFFFFFFu, acc, off);
        s[e] = 1.f / (1.f + expf(-(acc + bg[e] + bias[e])));
    }
    if (lane == 0) {
        int i0 = 0;
#pragma unroll
        for (int e = 1; e < Em; e++) if (s[e] > s[i0]) i0 = e;
        int i1 = -1;
#pragma unroll
        for (int e = 0; e < Em; e++) if (e != i0 && (i1 < 0 || s[e] > s[i1])) i1 = e;
        g_topi[2 * t] = i0;     g_topw[2 * t] = s[i0];
        g_topi[2 * t + 1] = i1; g_topw[2 * t + 1] = s[i1];
        atomicAdd(&g_cnt9[i0], 1);
        atomicAdd(&g_cnt9[i1], 1);
    }
}

// ================== kernel: routing (offsets + tile table + scatter), 1 block ==================
__global__ __launch_bounds__(1024) void k_route() {
    if (threadIdx.x == 0) {
        g_cnt9[8] = Tm;
        g_off9[8] = 0;
        int nt = 0;
        for (int rs = 0; rs < Tm; rs += TILE_M) g_tiles[nt++] = make_int2(8, rs);
        int p = Tm;
        for (int e = 0; e < Em; e++) {
            g_off9[e] = p;
            p += g_cnt9[e];
            for (int rs = 0; rs < g_cnt9[e]; rs += TILE_M) g_tiles[nt++] = make_int2(e, rs);
        }
        g_ntiles = nt;
    }
    __syncthreads();
#pragma unroll
    for (int r = 0; r < 2; ++r) {
        int t = threadIdx.x + r * 1024;
        g_tok[t] = t; // shared slots occupy [0, Tm)
#pragma unroll
        for (int k = 0; k < 2; k++) {
            int e = g_topi[2 * t + k];
            float w = g_topw[2 * t + k];
            int pos = atomicAdd(&g_fill[e], 1);
            int slot = g_off9[e] + pos;
            g_tok[slot] = t;
            g_slot[2 * t + k] = slot;
            g_cw[2 * t + k] = w;
        }
    }
}

// ================== grouped GEMM, 128x128 tile, HMMA m16n8k16 f32-acc (R8 config) ==================
// 256 threads = 8 warps in 4(m) x 2(n); each warp computes 32x64.
// 3-stage cp.async pipeline, one __syncthreads per K=64 chunk, 2 CTAs/SM.
// MODE 1: h = gelu(x @ W1^T + b1) -> g_h (fp16), K = 1024
// MODE 2: o2 = h @ W2^T + b2      -> g_o2 (fp32), K = 4096
template <int MODE>
__global__ __launch_bounds__(256, 2) void k_gemm(
    const float* __restrict__ b1, const float* __restrict__ bs1,
    const float* __restrict__ b2, const float* __restrict__ bs2)
{
    extern __shared__ char smem[];
    const int tid = threadIdx.x;
    const int lane = tid & 31, wid = tid >> 5;
    const int wm = wid >> 1, wn = wid & 1;

    int mt = blockIdx.x;
    if (mt >= g_ntiles) return;
    int2 tl = g_tiles[mt];
    const int e = tl.x, rs = tl.y;
    const int rows_valid = g_cnt9[e] - rs;
    const int slot_base = g_off9[e] + rs;
    const int nbase = blockIdx.y * 128;

    constexpr int K = (MODE == 1) ? Dm : Hm;
    constexpr int NK = K / 64;

    uint32_t sb = smem_u32(smem);

    const int crow = tid >> 1;
    const __half* Asrc;
    if (MODE == 1) {
        int tok = g_tok[slot_base + crow];
        Asrc = g_xh + (size_t)tok * Dm;
    } else {
        Asrc = g_h + (size_t)(slot_base + crow) * Hm;
    }
    const __half* Bsrc = ((MODE == 1) ? g_W1h : g_W2h)
                         + (size_t)e * HD + (size_t)(nbase + crow) * K;
    uint32_t cdst[4];
#pragma unroll
    for (int v = 0; v < 4; ++v) {
        int ch = (tid & 1) * 4 + v;
        cdst[v] = (uint32_t)crow * 128u + (uint32_t)((ch ^ (crow & 7)) << 4);
    }

    const int m4 = lane >> 3;
    const int aro = ((m4 & 1) << 3) + (lane & 7);
    const int aco = m4 >> 1;
    const int bro = ((m4 >> 1) << 3) + (lane & 7);
    const int bco = m4 & 1;

    float acc[2][8][4];
#pragma unroll
    for (int a = 0; a < 2; ++a)
#pragma unroll
        for (int b = 0; b < 8; ++b)
#pragma unroll
            for (int c = 0; c < 4; ++c) acc[a][b][c] = 0.f;

    auto issue = [&](int i) {
        uint32_t stg = sb + (uint32_t)(i % 3) * 32768u;
#pragma unroll
        for (int v = 0; v < 4; ++v) {
            int ch = (tid & 1) * 4 + v;
            cp_async16(stg + cdst[v], Asrc + i * 64 + ch * 8);
            cp_async16(stg + 16384u + cdst[v], Bsrc + i * 64 + ch * 8);
        }
        cp_commit();
    };

    issue(0);
    issue(1);

    for (int i = 0; i < NK; ++i) {
        if (i + 2 < NK) cp_wait<1>(); else cp_wait<0>();
        __syncthreads();
        if (i + 2 < NK) issue(i + 2);

        uint32_t stg = sb + (uint32_t)(i % 3) * 32768u;
        const uint32_t Ab = stg, Bb = stg + 16384u;
#pragma unroll
        for (int ks = 0; ks < 4; ++ks) {
            uint32_t afr[2][4];
#pragma unroll
            for (int t2 = 0; t2 < 2; ++t2) {
                int row = wm * 32 + t2 * 16 + aro;
                uint32_t ad = Ab + (uint32_t)row * 128u
                            + (uint32_t)(((ks * 2 + aco) ^ (row & 7)) << 4);
                ldsm4(afr[t2], ad);
            }
            uint32_t bfr[4][4];
#pragma unroll
            for (int p = 0; p < 4; ++p) {
                int row = wn * 64 + p * 16 + bro;
                uint32_t bd = Bb + (uint32_t)row * 128u
                            + (uint32_t)(((ks * 2 + bco) ^ (row & 7)) << 4);
                ldsm4(bfr[p], bd);
            }
#pragma unroll
            for (int t2 = 0; t2 < 2; ++t2)
#pragma unroll
                for (int nt = 0; nt < 8; ++nt)
                    mma16816(acc[t2][nt], afr[t2], &bfr[nt >> 1][(nt & 1) * 2]);
        }
    }

    // ---- epilogue ----
    const int g = lane >> 2, tg = lane & 3;
    const float* brow = (MODE == 1)
        ? ((e < Em) ? (b1 + (size_t)e * Hm) : bs1)
        : ((e < Em) ? (b2 + (size_t)e * Dm) : bs2);

#pragma unroll
    for (int t2 = 0; t2 < 2; ++t2) {
        int row0 = wm * 32 + t2 * 16 + g;
        int row1 = row0 + 8;
        bool v0 = row0 < rows_valid, v1 = row1 < rows_valid;
#pragma unroll
        for (int nt = 0; nt < 8; ++nt) {
            int col = nbase + wn * 64 + nt * 8 + tg * 2;
            float bv0 = brow[col], bv1 = brow[col + 1];
            const float* c = acc[t2][nt];
            if (MODE == 1) {
                if (v0) {
                    __half2 h = __floats2half2_rn(gelu_exact(c[0] + bv0), gelu_exact(c[1] + bv1));
                    *(__half2*)(g_h + (size_t)(slot_base + row0) * Hm + col) = h;
                }
                if (v1) {
                    __half2 h = __floats2half2_rn(gelu_exact(c[2] + bv0), gelu_exact(c[3] + bv1));
                    *(__half2*)(g_h + (size_t)(slot_base + row1) * Hm + col) = h;
                }
            } else {
                if (v0) {
                    float2 o = make_float2(c[0] + bv0, c[1] + bv1);
                    *(float2*)(g_o2 + (size_t)(slot_base + row0) * Dm + col) = o;
                }
                if (v1) {
                    float2 o = make_float2(c[2] + bv0, c[3] + bv1);
                    *(float2*)(g_o2 + (size_t)(slot_base + row1) * Dm + col) = o;
                }
            }
        }
    }
}

// ================== kernel: combine (deterministic, no atomics) ==================
__global__ void k_combine(float* __restrict__ out) {
    int t = blockIdx.x;
    int d = threadIdx.x * 4;
    float4 sh = *(const float4*)(g_o2 + (size_t)t * Dm + d);
    int s0 = g_slot[2 * t], s1 = g_slot[2 * t + 1];
    float w0 = g_cw[2 * t], w1 = g_cw[2 * t + 1];
    float4 a = *(const float4*)(g_o2 + (size_t)s0 * Dm + d);
    float4 b = *(const float4*)(g_o2 + (size_t)s1 * Dm + d);
    float4 o;
    o.x = sh.x + w0 * a.x + w1 * b.x;
    o.y = sh.y + w0 * a.y + w1 * b.y;
    o.z = sh.z + w0 * a.z + w1 * b.z;
    o.w = sh.w + w0 * a.w + w1 * b.w;
    *(float4*)(out + (size_t)t * Dm + d) = o;
}

// ================== host launcher ==================
// Side stream: convert1 -> convert2 SERIAL (convert1 gets full DRAM BW, finishes ~35us;
// convert2 then streams underneath GEMM1 which is DRAM-light).
// Main stream: zero/gating/route overlap convert1; GEMM1 waits ev1; GEMM2 waits ev2.
extern "C" void kernel_launch(void* const* d_in, const int* in_sizes, int n_in,
                              void* d_out, int out_size) {
    const float* x    = (const float*)d_in[0];
    const float* Wg   = (const float*)d_in[1];
    const float* bg   = (const float*)d_in[2];
    const float* bias = (const float*)d_in[3];
    const float* W1   = (const float*)d_in[4];
    const float* b1   = (const float*)d_in[5];
    const float* W2   = (const float*)d_in[6];
    const float* b2   = (const float*)d_in[7];
    const float* Ws1  = (const float*)d_in[8];
    const float* bs1  = (const float*)d_in[9];
    const float* Ws2  = (const float*)d_in[10];
    const float* bs2  = (const float*)d_in[11];
    float* out = (float*)d_out;
    (void)in_sizes; (void)n_in; (void)out_size;

    // host-side resources, created once (no device memory involved)
    static cudaStream_t s1 = nullptr;
    static cudaEvent_t evA = nullptr, ev1 = nullptr, ev2 = nullptr;
    if (s1 == nullptr) {
        cudaStreamCreateWithFlags(&s1, cudaStreamNonBlocking);
        cudaEventCreateWithFlags(&evA, cudaEventDisableTiming);
        cudaEventCreateWithFlags(&ev1, cudaEventDisableTiming);
        cudaEventCreateWithFlags(&ev2, cudaEventDisableTiming);
        cudaFuncSetAttribute(k_gemm<1>, cudaFuncAttributeMaxDynamicSharedMemorySize, SMEM_BYTES);
        cudaFuncSetAttribute(k_gemm<2>, cudaFuncAttributeMaxDynamicSharedMemorySize, SMEM_BYTES);
    }

    const int cvt_blocks = (int)(((long)NG * HD / 4 + 255) / 256);

    // fork side stream: convert1 then convert2 (serial on s1)
    cudaEventRecord(evA, 0);
    cudaStreamWaitEvent(s1, evA, 0);
    k_convert1<<<cvt_blocks, 256, 0, s1>>>(W1, Ws1);
    cudaEventRecord(ev1, s1);
    k_convert2<<<cvt_blocks, 256, 0, s1>>>(W2, Ws2);
    cudaEventRecord(ev2, s1);

    // main stream: routing pipeline (overlaps convert1)
    k_zero<<<(PADROWS + 255) / 256, 256>>>();
    k_gating<<<Tm / 8, 256>>>(x, Wg, bg, bias);
    k_route<<<1, 1024>>>();

    // GEMM1 needs convert1 only; convert2 hides under GEMM1
    cudaStreamWaitEvent(0, ev1, 0);
    k_gemm<1><<<dim3(MAXTILES, Hm / 128), 256, SMEM_BYTES>>>(b1, bs1, b2, bs2);
    // GEMM2 needs GEMM1 (stream order) + convert2
    cudaStreamWaitEvent(0, ev2, 0);
    k_gemm<2><<<dim3(MAXTILES, Dm / 128), 256, SMEM_BYTES>>>(b1, bs1, b2, bs2);
    k_combine<<<Tm, 256>>>(out);
}